// round 4
// baseline (speedup 1.0000x reference)
#include <cuda_runtime.h>

typedef unsigned long long u64;

#define NP 64
#define NCOLS 500000
#define BCOLS 256                               /* cols per block */
#define NB    ((NCOLS + BCOLS - 1) / BCOLS)     /* 1954 blocks */
#define NANG 2016

// RT[r*64 + i] = mus[i] * R[i][r]  (R = product of Givens rotations)
__device__ float d_RT[NP * NP];

// ---------------------------------------------------------------------------
// Kernel 1: build the 64x64 combined rotation+scale matrix.
// Thread j owns column j, held in smem (stride-64 -> conflict-free).
// vt carried in a register (the only true dependency chain: 1 FFMA/rotation);
// m[ib+1] is prefetched BEFORE m[ib] is stored so the LDS is never ordered
// behind the STS. Small loop body -> I$-resident.
// ---------------------------------------------------------------------------
__global__ void __launch_bounds__(64)
build_R_kernel(const float* __restrict__ angles, const float* __restrict__ mus) {
    __shared__ float2 cs[NANG];
    __shared__ float  M[NP * NP];
    const int j = threadIdx.x;

    for (int k = j; k < NANG; k += NP) {
        float s, c;
        sincosf(angles[k], &s, &c);
        cs[k] = make_float2(c, s);
    }
    #pragma unroll
    for (int i = 0; i < NP; i++) M[i * NP + j] = (i == j) ? 1.0f : 0.0f;
    __syncthreads();

    float* col = &M[j];                    // stride-64 column
    int k = 0;
    for (int it = 0; it < NP - 1; it++) {
        float vt = col[it * NP];
        float mb = col[(it + 1) * NP];
        for (int ib = it + 1; ib < NP; ib++, k++) {
            float2 c_s = cs[k];
            float  mbn = (ib + 1 < NP) ? col[(ib + 1) * NP] : 0.0f;  // prefetch
            float  nb  = c_s.y * vt + c_s.x * mb;   // vb' = s*vt + c*vb
            vt         = c_s.x * vt - c_s.y * mb;   // vt' = c*vt - s*vb
            col[ib * NP] = nb;
            mb = mbn;
        }
        col[it * NP] = vt;
    }
    __syncthreads();
    // thread j writes row j of RT: RT[j][i] = M[i][j] * mus[i]
    for (int i = 0; i < NP; i++)
        d_RT[j * NP + i] = M[i * NP + j] * mus[i];
}

// ---------------------------------------------------------------------------
// Kernel 2: Y = M @ X.  Block: 64 rows x 256 cols, 8 warps, 2 blocks/SM.
// Thread: 8 rows x 8 cols. Per K: 2 LDG.128 (X, pointer-bumped, depth-2
// prefetch) + 4 LDS.128 (R, prefetched one K ahead) -> 32 FFMA2.
// ---------------------------------------------------------------------------
__device__ __forceinline__ void fma2(u64& d, u64 a, u64 b) {
    asm("fma.rn.f32x2 %0, %1, %2, %0;" : "+l"(d) : "l"(a), "l"(b));
}
__device__ __forceinline__ u64 dup2(float v) {
    u64 r;
    asm("mov.b64 %0, {%1, %1};" : "=l"(r) : "r"(__float_as_uint(v)));
    return r;
}

__global__ void __launch_bounds__(256, 2)
gemm_kernel(const float* __restrict__ X, float* __restrict__ out) {
    __shared__ __align__(16) u64 sR[NP * NP];   // duplicated (v,v) pairs, 32 KB

    const int tid = threadIdx.x;
    const float4* R4 = (const float4*)d_RT;
    for (int t = tid; t < NP * NP / 4; t += 256) {
        float4 v = R4[t];
        sR[t * 4 + 0] = dup2(v.x);
        sR[t * 4 + 1] = dup2(v.y);
        sR[t * 4 + 2] = dup2(v.z);
        sR[t * 4 + 3] = dup2(v.w);
    }
    __syncthreads();

    const int lane = tid & 31;
    const int wid  = tid >> 5;
    const int colA = blockIdx.x * BCOLS + lane * 4;
    const int colB = colA + 128;
    const bool actA = (colA < NCOLS);
    const bool actB = (colB < NCOLS);
    const int colAc = actA ? colA : (NCOLS - 4);
    const int colBc = actB ? colB : (NCOLS - 4);

    const size_t rowb = (size_t)NCOLS * 4;      // row stride in bytes
    const char* pA = (const char*)(X + colAc);  // prefetch cursors
    const char* pB = (const char*)(X + colBc);
    const ulonglong2* sR2 = (const ulonglong2*)sR;
    const int rbase = wid * 4;

    u64 aA[8][2], aB[8][2];
    #pragma unroll
    for (int il = 0; il < 8; il++) {
        aA[il][0] = aA[il][1] = 0ULL;
        aB[il][0] = aB[il][1] = 0ULL;
    }

    // X pipeline: depth 2
    ulonglong2 xa[2], xb[2];
    xa[0] = *(const ulonglong2*)pA;  xb[0] = *(const ulonglong2*)pB;
    pA += rowb; pB += rowb;
    xa[1] = *(const ulonglong2*)pA;  xb[1] = *(const ulonglong2*)pB;
    pA += rowb; pB += rowb;

    // R pipeline: depth 1
    ulonglong2 rvc[4];
    #pragma unroll
    for (int u = 0; u < 4; u++) rvc[u] = sR2[rbase + u];

    #pragma unroll 4
    for (int k = 0; k < NP; k++) {
        // prefetch X row k+2 (predicated off for the last two iterations)
        ulonglong2 na, nb;
        const bool pf = (k < NP - 2);
        if (pf) { na = *(const ulonglong2*)pA; nb = *(const ulonglong2*)pB; }
        pA += rowb; pB += rowb;

        // prefetch R row k+1 (clamped)
        const int kn = (k + 1 < NP) ? (k + 1) : k;
        ulonglong2 rvn[4];
        #pragma unroll
        for (int u = 0; u < 4; u++) rvn[u] = sR2[kn * 32 + rbase + u];

        const ulonglong2 cA = xa[k & 1], cB = xb[k & 1];
        #pragma unroll
        for (int il = 0; il < 8; il++) {
            const u64 Rd = (il & 1) ? rvc[il >> 1].y : rvc[il >> 1].x;
            fma2(aA[il][0], Rd, cA.x);
            fma2(aA[il][1], Rd, cA.y);
            fma2(aB[il][0], Rd, cB.x);
            fma2(aB[il][1], Rd, cB.y);
        }
        if (pf) { xa[k & 1] = na; xb[k & 1] = nb; }
        #pragma unroll
        for (int u = 0; u < 4; u++) rvc[u] = rvn[u];
    }

    #pragma unroll
    for (int il = 0; il < 8; il++) {
        const int i = wid * 8 + il;
        if (actA) {
            ulonglong2 v; v.x = aA[il][0]; v.y = aA[il][1];
            *(ulonglong2*)(out + (size_t)i * NCOLS + colA) = v;
        }
        if (actB) {
            ulonglong2 v; v.x = aB[il][0]; v.y = aB[il][1];
            *(ulonglong2*)(out + (size_t)i * NCOLS + colB) = v;
        }
    }
}

// ---------------------------------------------------------------------------
extern "C" void kernel_launch(void* const* d_in, const int* in_sizes, int n_in,
                              void* d_out, int out_size) {
    const float* X      = (const float*)d_in[0];
    const float* angles = (const float*)d_in[1];
    const float* mus    = (const float*)d_in[2];
    float*       out    = (float*)d_out;

    build_R_kernel<<<1, NP>>>(angles, mus);
    gemm_kernel<<<NB, 256>>>(X, out);
}

// round 5
// speedup vs baseline: 1.7313x; 1.7313x over previous
#include <cuda_runtime.h>

typedef unsigned long long u64;

#define NP 64
#define NCOLS 500000
#define BCOLS 256
#define NB    ((NCOLS + BCOLS - 1) / BCOLS)   /* 1954 */
#define NANG 2016
#define KCH   16                              /* K rows per staged chunk */
#define NCH   (NP / KCH)                      /* 4 chunks */

// RT[r*64 + i] = mus[i] * R[i][r]
__device__ float d_RT[NP * NP];

// ---------------------------------------------------------------------------
// Kernel 1: build 64x64 combined rotation+scale matrix.
// Thread j owns column j in smem (stride-64, conflict-free). The vt chain is
// ONE FFMA per rotation: s*mb and c*mb are precomputed one iteration early,
// mb is prefetched distance-2 from a padded array (no guards on the fast path).
// ---------------------------------------------------------------------------
__global__ void __launch_bounds__(64)
build_R_kernel(const float* __restrict__ angles, const float* __restrict__ mus) {
    __shared__ float2 cs[NANG + 2];
    __shared__ float  M[(NP + 2) * NP];     // 2 pad rows for distance-2 prefetch
    const int j = threadIdx.x;

    for (int k = j; k < NANG; k += NP) {
        float s, c;
        sincosf(angles[k], &s, &c);
        cs[k] = make_float2(c, s);
    }
    if (j < 2) cs[NANG + j] = make_float2(0.f, 0.f);
    #pragma unroll
    for (int i = 0; i < NP + 2; i++) M[i * NP + j] = (i == j) ? 1.0f : 0.0f;
    __syncthreads();

    float* col = &M[j];
    int k = 0;
    for (int it = 0; it < NP - 1; it++) {
        const int n = NP - 1 - it;          // rotations this sweep
        float vt     = col[it * NP];
        float mb_nxt = col[(it + 2) * NP];  // value for iter r=1
        float2 csc   = cs[k];
        float mb0    = col[(it + 1) * NP];
        float smb    = csc.y * mb0;         // s*mb for iter 0
        float cmb    = csc.x * mb0;         // c*mb for iter 0
        for (int r = 0; r < n; r++) {
            float  mb2   = col[(it + 3 + r) * NP];   // prefetch distance 2 (pad-safe)
            float2 csn   = cs[k + r + 1];            // next (c,s) (pad-safe)
            float  nb    = fmaf(csc.y, vt, cmb);     // vb' = s*vt + c*vb
            vt           = fmaf(csc.x, vt, -smb);    // vt' = c*vt - s*vb  (chain: 1 FFMA)
            col[(it + 1 + r) * NP] = nb;
            smb = csn.y * mb_nxt;                    // for next iter
            cmb = csn.x * mb_nxt;
            mb_nxt = mb2;
            csc = csn;
        }
        col[it * NP] = vt;
        k += n;
    }
    __syncthreads();
    for (int i = 0; i < NP; i++)
        d_RT[j * NP + i] = M[i * NP + j] * mus[i];
}

// ---------------------------------------------------------------------------
// cp.async helpers
// ---------------------------------------------------------------------------
__device__ __forceinline__ void cpa16(void* smem, const void* g) {
    unsigned s = (unsigned)__cvta_generic_to_shared(smem);
    asm volatile("cp.async.cg.shared.global [%0], [%1], 16;\n" :: "r"(s), "l"(g));
}
__device__ __forceinline__ void cpa_commit() {
    asm volatile("cp.async.commit_group;\n");
}
template <int N>
__device__ __forceinline__ void cpa_wait() {
    asm volatile("cp.async.wait_group %0;\n" :: "n"(N));
}

__device__ __forceinline__ void fma2(u64& d, u64 a, u64 b) {
    asm("fma.rn.f32x2 %0, %1, %2, %0;" : "+l"(d) : "l"(a), "l"(b));
}
__device__ __forceinline__ u64 dup2(float v) {
    u64 r;
    asm("mov.b64 %0, {%1, %1};" : "=l"(r) : "r"(__float_as_uint(v)));
    return r;
}

// ---------------------------------------------------------------------------
// Kernel 2: Y = M @ X.  Block: 64 rows x 256 cols, 8 warps, 2 blocks/SM.
// X staged through smem in 16-row chunks via cp.async (double-buffered,
// distance-2 pipeline). Thread: 8 rows x 8 cols.
// Per k: 2 LDS.128 (X) + 4 LDS.128 (R broadcast) -> 32 FFMA2.
// ---------------------------------------------------------------------------
__global__ void __launch_bounds__(256, 2)
gemm_kernel(const float* __restrict__ X, float* __restrict__ out) {
    __shared__ __align__(16) u64   sR[NP * NP];          // dup (v,v) pairs, 32 KB
    __shared__ __align__(16) float sX[2][KCH * BCOLS];   // 2 x 16 KB

    const int tid = threadIdx.x;
    const float4* R4 = (const float4*)d_RT;
    for (int t = tid; t < NP * NP / 4; t += 256) {
        float4 v = R4[t];
        sR[t * 4 + 0] = dup2(v.x);
        sR[t * 4 + 1] = dup2(v.y);
        sR[t * 4 + 2] = dup2(v.z);
        sR[t * 4 + 3] = dup2(v.w);
    }

    const int lane = tid & 31;
    const int wid  = tid >> 5;
    const int col0 = blockIdx.x * BCOLS;

    // cp.async mapping: thread -> row (tid>>4) in chunk, 16 cols at (tid&15)*16
    const int lrow = tid >> 4;                 // 0..15
    const int gcol = col0 + (tid & 15) * 16;
    const int c0 = min(gcol +  0, NCOLS - 4);  // per-16B clamp (tail block)
    const int c1 = min(gcol +  4, NCOLS - 4);
    const int c2 = min(gcol +  8, NCOLS - 4);
    const int c3 = min(gcol + 12, NCOLS - 4);
    float* sdst0 = &sX[0][lrow * BCOLS + (tid & 15) * 16];
    float* sdst1 = &sX[1][lrow * BCOLS + (tid & 15) * 16];

    {   // prefetch chunks 0 and 1
        size_t ro = (size_t)lrow * NCOLS;
        cpa16(sdst0 +  0, X + ro + c0);  cpa16(sdst0 +  4, X + ro + c1);
        cpa16(sdst0 +  8, X + ro + c2);  cpa16(sdst0 + 12, X + ro + c3);
        cpa_commit();
        ro += (size_t)KCH * NCOLS;
        cpa16(sdst1 +  0, X + ro + c0);  cpa16(sdst1 +  4, X + ro + c1);
        cpa16(sdst1 +  8, X + ro + c2);  cpa16(sdst1 + 12, X + ro + c3);
        cpa_commit();
    }

    u64 aA[8][2], aB[8][2];
    #pragma unroll
    for (int il = 0; il < 8; il++) {
        aA[il][0] = aA[il][1] = 0ULL;
        aB[il][0] = aB[il][1] = 0ULL;
    }

    const int rbase = wid * 4;

    #pragma unroll 1
    for (int ch = 0; ch < NCH; ch++) {
        if (ch == NCH - 1) cpa_wait<0>(); else cpa_wait<1>();
        __syncthreads();

        const ulonglong2* xc  = (const ulonglong2*)&sX[ch & 1][0];
        const ulonglong2* sR2 = (const ulonglong2*)sR;
        #pragma unroll
        for (int k = 0; k < KCH; k++) {
            const ulonglong2 cA = xc[k * (BCOLS / 4) + lane];
            const ulonglong2 cB = xc[k * (BCOLS / 4) + lane + 32];
            ulonglong2 rv[4];
            #pragma unroll
            for (int u = 0; u < 4; u++)
                rv[u] = sR2[(ch * KCH + k) * 32 + rbase + u];
            #pragma unroll
            for (int il = 0; il < 8; il++) {
                const u64 Rd = (il & 1) ? rv[il >> 1].y : rv[il >> 1].x;
                fma2(aA[il][0], Rd, cA.x);
                fma2(aA[il][1], Rd, cA.y);
                fma2(aB[il][0], Rd, cB.x);
                fma2(aB[il][1], Rd, cB.y);
            }
        }
        __syncthreads();   // all reads of this buffer done before refill

        if (ch + 2 < NCH) {
            size_t ro = (size_t)(lrow + (ch + 2) * KCH) * NCOLS;
            float* d = (ch & 1) ? sdst1 : sdst0;
            cpa16(d +  0, X + ro + c0);  cpa16(d +  4, X + ro + c1);
            cpa16(d +  8, X + ro + c2);  cpa16(d + 12, X + ro + c3);
        }
        cpa_commit();      // commit every iteration to keep group counts aligned
    }

    const int colA = col0 + lane * 4;
    const int colB = colA + 128;
    #pragma unroll
    for (int il = 0; il < 8; il++) {
        const int i = wid * 8 + il;
        if (colA < NCOLS) {
            ulonglong2 v; v.x = aA[il][0]; v.y = aA[il][1];
            *(ulonglong2*)(out + (size_t)i * NCOLS + colA) = v;
        }
        if (colB < NCOLS) {
            ulonglong2 v; v.x = aB[il][0]; v.y = aB[il][1];
            *(ulonglong2*)(out + (size_t)i * NCOLS + colB) = v;
        }
    }
}

// ---------------------------------------------------------------------------
extern "C" void kernel_launch(void* const* d_in, const int* in_sizes, int n_in,
                              void* d_out, int out_size) {
    const float* X      = (const float*)d_in[0];
    const float* angles = (const float*)d_in[1];
    const float* mus    = (const float*)d_in[2];
    float*       out    = (float*)d_out;

    build_R_kernel<<<1, NP>>>(angles, mus);
    gemm_kernel<<<NB, 256>>>(X, out);
}